// round 2
// baseline (speedup 1.0000x reference)
#include <cuda_runtime.h>
#include <cstdint>
#include <math.h>

// B=64, S=512, Q=800, K=4, D=64  ->  GEMM: C[M=32768, N=64] = A[M,800] * Wq^T[800,64]
#define MDIM   32768
#define KDIM   800
#define NDIM   64
#define TM     128
#define TK     32
#define NITER  (KDIM / TK)   // 25
#define THREADS 256

// ---------------------------------------------------------------------------
// helpers
// ---------------------------------------------------------------------------
__device__ __forceinline__ uint32_t f2tf(float x) {
    uint32_t r;
    asm("cvt.rna.tf32.f32 %0, %1;" : "=r"(r) : "f"(x));
    return r;
}

__device__ __forceinline__ void ldsm4(uint32_t& r0, uint32_t& r1, uint32_t& r2, uint32_t& r3,
                                      uint32_t addr) {
    asm volatile("ldmatrix.sync.aligned.m8n8.x4.shared.b16 {%0,%1,%2,%3}, [%4];"
                 : "=r"(r0), "=r"(r1), "=r"(r2), "=r"(r3) : "r"(addr));
}

__device__ __forceinline__ void mma_tf32(float* c,
                                         uint32_t a0, uint32_t a1, uint32_t a2, uint32_t a3,
                                         uint32_t b0, uint32_t b1) {
    asm volatile(
        "mma.sync.aligned.m16n8k8.row.col.f32.tf32.tf32.f32 "
        "{%0,%1,%2,%3}, {%4,%5,%6,%7}, {%8,%9}, {%0,%1,%2,%3};"
        : "+f"(c[0]), "+f"(c[1]), "+f"(c[2]), "+f"(c[3])
        : "r"(a0), "r"(a1), "r"(a2), "r"(a3), "r"(b0), "r"(b1));
}

// ---------------------------------------------------------------------------
// kernel
// ---------------------------------------------------------------------------
__global__ __launch_bounds__(THREADS)
void ordinal_embed_kernel(const float* __restrict__ q,
                          const int*   __restrict__ rdat,
                          const float* __restrict__ Wq,   // [64, 800] row-major
                          const float* __restrict__ bq,   // [64]
                          const float* __restrict__ Wr,   // [4]
                          const float* __restrict__ br,   // [1]
                          float*       __restrict__ out)  // [32768, 64]
{
    // tf32-converted, XOR-swizzled tiles.
    // element (row, k) lives at row*TK + (k ^ ((row&7)*4))  (word units)
    __shared__ uint32_t As[2][TM * TK];    // 32 KB
    __shared__ uint32_t Bs[2][NDIM * TK];  // 16 KB

    const int tid  = threadIdx.x;
    const int lane = tid & 31;
    const int w    = tid >> 5;         // warp id 0..7, warp handles rows [w*16, w*16+16)
    const int bm   = blockIdx.x;

    float acc[8][4];
    #pragma unroll
    for (int nt = 0; nt < 8; ++nt)
        #pragma unroll
        for (int i = 0; i < 4; ++i)
            acc[nt][i] = 0.0f;

    const uint32_t asBase = (uint32_t)__cvta_generic_to_shared(&As[0][0]);
    const uint32_t bsBase = (uint32_t)__cvta_generic_to_shared(&Bs[0][0]);

    // ---- per-thread staging coordinates ------------------------------------
    // A tile: 128 rows x 32 floats = 1024 x 16B chunks -> 4 per thread
    // B tile: 64 rows  x 32 floats = 512  x 16B chunks -> 2 per thread
    const float* aRowBase = q + (size_t)bm * TM * KDIM;
    const float* aptr[4]; uint32_t asoff[4];
    const float* bptr[2]; uint32_t bsoff[2];
    #pragma unroll
    for (int i = 0; i < 4; ++i) {
        int ch = tid + THREADS * i;
        int m  = ch >> 3;
        int kq = (ch & 7) * 4;
        aptr[i]  = aRowBase + (size_t)m * KDIM + kq;
        asoff[i] = (uint32_t)(m * TK + (kq ^ ((m & 7) * 4))) * 4u;
    }
    #pragma unroll
    for (int i = 0; i < 2; ++i) {
        int ch = tid + THREADS * i;
        int n  = ch >> 3;
        int kq = (ch & 7) * 4;
        bptr[i]  = Wq + (size_t)n * KDIM + kq;
        bsoff[i] = (uint32_t)(n * TK + (kq ^ ((n & 7) * 4))) * 4u;
    }

    // ---- ldmatrix lane coordinates -----------------------------------------
    // A x4 -> {a0,a1,a2,a3}: lanes 0-7 rows 0-7 @k, 8-15 rows 8-15 @k,
    //                        16-23 rows 0-7 @k+4, 24-31 rows 8-15 @k+4
    const int rA = w * 16 + (lane & 15);
    const int cA = (lane >> 4) << 2;       // 0 or 4
    const int xA = (rA & 7) * 4;
    // B x4 -> {b0(2p), b1(2p), b0(2p+1), b1(2p+1)}
    const int nBlow = (lane & 7) + ((lane >> 4) & 1) * 8;   // + p*16 later
    const int cB    = ((lane >> 3) & 1) * 4;                // 0 or 4

    float4 ra[4]; float4 rb[2];

    // ---- prologue load ----
    #pragma unroll
    for (int i = 0; i < 4; ++i) ra[i] = *reinterpret_cast<const float4*>(aptr[i]);
    #pragma unroll
    for (int i = 0; i < 2; ++i) rb[i] = *reinterpret_cast<const float4*>(bptr[i]);

    for (int it = 0; it < NITER; ++it) {
        const uint32_t aB = asBase + (uint32_t)(it & 1) * (TM * TK * 4u);
        const uint32_t bB = bsBase + (uint32_t)(it & 1) * (NDIM * TK * 4u);

        // ---- cvt + store staged registers into smem ----
        #pragma unroll
        for (int i = 0; i < 4; ++i) {
            uint32_t v0 = f2tf(ra[i].x), v1 = f2tf(ra[i].y),
                     v2 = f2tf(ra[i].z), v3 = f2tf(ra[i].w);
            asm volatile("st.shared.v4.b32 [%0], {%1,%2,%3,%4};"
                         :: "r"(aB + asoff[i]), "r"(v0), "r"(v1), "r"(v2), "r"(v3));
        }
        #pragma unroll
        for (int i = 0; i < 2; ++i) {
            uint32_t v0 = f2tf(rb[i].x), v1 = f2tf(rb[i].y),
                     v2 = f2tf(rb[i].z), v3 = f2tf(rb[i].w);
            asm volatile("st.shared.v4.b32 [%0], {%1,%2,%3,%4};"
                         :: "r"(bB + bsoff[i]), "r"(v0), "r"(v1), "r"(v2), "r"(v3));
        }
        __syncthreads();

        // ---- prefetch next k-tile into registers (consumed next iter) ----
        if (it + 1 < NITER) {
            const int koff = (it + 1) * TK;
            #pragma unroll
            for (int i = 0; i < 4; ++i)
                ra[i] = *reinterpret_cast<const float4*>(aptr[i] + koff);
            #pragma unroll
            for (int i = 0; i < 2; ++i)
                rb[i] = *reinterpret_cast<const float4*>(bptr[i] + koff);
        }

        // ---- compute this k-tile: 4 x (1 A-ldsm + 4 B-ldsm + 8 mma) ----
        #pragma unroll
        for (int k8 = 0; k8 < 4; ++k8) {
            uint32_t af0, af1, af2, af3;
            {
                int c = k8 * 8 + cA;
                ldsm4(af0, af1, af2, af3,
                      aB + (uint32_t)(rA * TK + (c ^ xA)) * 4u);
            }
            uint32_t bf[4][4];
            #pragma unroll
            for (int p = 0; p < 4; ++p) {
                int n = p * 16 + nBlow;
                int c = k8 * 8 + cB;
                ldsm4(bf[p][0], bf[p][1], bf[p][2], bf[p][3],
                      bB + (uint32_t)(n * TK + (c ^ ((n & 7) * 4))) * 4u);
            }
            #pragma unroll
            for (int nt = 0; nt < 8; ++nt)
                mma_tf32(acc[nt], af0, af1, af2, af3,
                         bf[nt >> 1][(nt & 1) * 2], bf[nt >> 1][(nt & 1) * 2 + 1]);
        }
        // no trailing sync: sts(it+1) writes the opposite buffer; the barrier
        // at the top of iteration it already ordered it vs compute(it-1).
    }

    // ---- epilogue: gate(r) * acc + bq ----
    const float wr0 = Wr[0], wr1 = Wr[1], wr2 = Wr[2], wr3 = Wr[3];
    const float brv = br[0];

    const int rbase = bm * TM + w * 16 + (lane >> 2);
    #pragma unroll
    for (int h = 0; h < 2; ++h) {
        const int row = rbase + h * 8;
        const float rf = (float)rdat[row];
        float s = brv;
        s += fmaxf(1.0f - fabsf(0.0f - rf) * (1.0f / 3.0f), 0.0f) * wr0;
        s += fmaxf(1.0f - fabsf(1.0f - rf) * (1.0f / 3.0f), 0.0f) * wr1;
        s += fmaxf(1.0f - fabsf(2.0f - rf) * (1.0f / 3.0f), 0.0f) * wr2;
        s += fmaxf(1.0f - fabsf(3.0f - rf) * (1.0f / 3.0f), 0.0f) * wr3;
        const float gate = 1.0f / (1.0f + expf(-s));

        #pragma unroll
        for (int nt = 0; nt < 8; ++nt) {
            const int col = nt * 8 + (lane & 3) * 2;
            float2 v;
            v.x = acc[nt][h * 2 + 0] * gate + bq[col];
            v.y = acc[nt][h * 2 + 1] * gate + bq[col + 1];
            *reinterpret_cast<float2*>(out + (size_t)row * NDIM + col) = v;
        }
    }
}

// ---------------------------------------------------------------------------
// launch
// ---------------------------------------------------------------------------
extern "C" void kernel_launch(void* const* d_in, const int* in_sizes, int n_in,
                              void* d_out, int out_size) {
    const float* q    = (const float*)d_in[0];   // [64,512,800] f32
    const int*   rdat = (const int*)  d_in[1];   // [64,512]     i32
    const float* Wq   = (const float*)d_in[2];   // [64,800]     f32
    const float* bq   = (const float*)d_in[3];   // [64]         f32
    const float* Wr   = (const float*)d_in[4];   // [1,4]        f32
    const float* br   = (const float*)d_in[5];   // [1]          f32
    float* out = (float*)d_out;                  // [64,512,64]  f32

    ordinal_embed_kernel<<<MDIM / TM, THREADS>>>(q, rdat, Wq, bq, Wr, br, out);
}

// round 3
// speedup vs baseline: 1.6491x; 1.6491x over previous
#include <cuda_runtime.h>
#include <cstdint>
#include <math.h>

// B=64, S=512, Q=800, K=4, D=64  ->  GEMM: C[M=32768, N=64] = A[M,800] * Wq^T[800,64]
#define MDIM    32768
#define KDIM    800
#define NDIM    64
#define TM      128
#define TK      32
#define NITER   (KDIM / TK)   // 25
#define THREADS 256
#define STAGES  4

#define A_BYTES (TM * TK * 4)            // 16384
#define B_BYTES (NDIM * TK * 4)          //  8192
#define STAGE_BYTES (A_BYTES + B_BYTES)  // 24576
#define SMEM_TOTAL (STAGES * STAGE_BYTES)

// ---------------------------------------------------------------------------
// helpers
// ---------------------------------------------------------------------------
__device__ __forceinline__ uint32_t f2tf(float x) {
    uint32_t r;
    asm("cvt.rna.tf32.f32 %0, %1;" : "=r"(r) : "f"(x));
    return r;
}
__device__ __forceinline__ uint32_t u2tf(uint32_t bits) {
    return f2tf(__uint_as_float(bits));
}

__device__ __forceinline__ void cp16(uint32_t dst, const void* src) {
    asm volatile("cp.async.cg.shared.global [%0], [%1], 16;" :: "r"(dst), "l"(src));
}

__device__ __forceinline__ void ldsm4(uint32_t& r0, uint32_t& r1, uint32_t& r2, uint32_t& r3,
                                      uint32_t addr) {
    asm volatile("ldmatrix.sync.aligned.m8n8.x4.shared.b16 {%0,%1,%2,%3}, [%4];"
                 : "=r"(r0), "=r"(r1), "=r"(r2), "=r"(r3) : "r"(addr));
}

__device__ __forceinline__ void mma_tf32(float* c,
                                         uint32_t a0, uint32_t a1, uint32_t a2, uint32_t a3,
                                         uint32_t b0, uint32_t b1) {
    asm volatile(
        "mma.sync.aligned.m16n8k8.row.col.f32.tf32.tf32.f32 "
        "{%0,%1,%2,%3}, {%4,%5,%6,%7}, {%8,%9}, {%0,%1,%2,%3};"
        : "+f"(c[0]), "+f"(c[1]), "+f"(c[2]), "+f"(c[3])
        : "r"(a0), "r"(a1), "r"(a2), "r"(a3), "r"(b0), "r"(b1));
}

// ---------------------------------------------------------------------------
// kernel
// ---------------------------------------------------------------------------
__global__ __launch_bounds__(THREADS)
void ordinal_embed_kernel(const float* __restrict__ q,
                          const int*   __restrict__ rdat,
                          const float* __restrict__ Wq,   // [64, 800] row-major
                          const float* __restrict__ bq,   // [64]
                          const float* __restrict__ Wr,   // [4]
                          const float* __restrict__ br,   // [1]
                          float*       __restrict__ out)  // [32768, 64]
{
    // Dynamic smem: STAGES x { A[128x32] f32 swizzled, B[64x32] f32 swizzled }
    // element (row, k) lives at row*TK + (k ^ ((row&7)*4))  (word units)
    extern __shared__ uint8_t smem[];
    const uint32_t smemBase = (uint32_t)__cvta_generic_to_shared(smem);

    const int tid  = threadIdx.x;
    const int lane = tid & 31;
    const int w    = tid >> 5;         // warp 0..7 -> rows [w*16, w*16+16)
    const int bm   = blockIdx.x;

    float acc[8][4];
    #pragma unroll
    for (int nt = 0; nt < 8; ++nt)
        #pragma unroll
        for (int i = 0; i < 4; ++i)
            acc[nt][i] = 0.0f;

    // ---- per-thread staging coordinates ------------------------------------
    // A tile: 1024 x 16B chunks -> 4 per thread; B tile: 512 chunks -> 2 per thread
    const float* aRowBase = q + (size_t)bm * TM * KDIM;
    const float* aptr[4]; uint32_t asoff[4];
    const float* bptr[2]; uint32_t bsoff[2];
    #pragma unroll
    for (int i = 0; i < 4; ++i) {
        int ch = tid + THREADS * i;
        int m  = ch >> 3;
        int kq = (ch & 7) * 4;
        aptr[i]  = aRowBase + (size_t)m * KDIM + kq;
        asoff[i] = (uint32_t)(m * TK + (kq ^ ((m & 7) * 4))) * 4u;
    }
    #pragma unroll
    for (int i = 0; i < 2; ++i) {
        int ch = tid + THREADS * i;
        int n  = ch >> 3;
        int kq = (ch & 7) * 4;
        bptr[i]  = Wq + (size_t)n * KDIM + kq;
        bsoff[i] = (uint32_t)(n * TK + (kq ^ ((n & 7) * 4))) * 4u + A_BYTES;
    }

    #define STAGE(IT)                                                       \
    do {                                                                    \
        const uint32_t _sb = smemBase + ((IT) % STAGES) * STAGE_BYTES;      \
        const int _k0 = (IT) * TK;                                          \
        _Pragma("unroll")                                                   \
        for (int i = 0; i < 4; ++i)                                         \
            cp16(_sb + asoff[i], aptr[i] + _k0);                            \
        _Pragma("unroll")                                                   \
        for (int i = 0; i < 2; ++i)                                         \
            cp16(_sb + bsoff[i], bptr[i] + _k0);                            \
        asm volatile("cp.async.commit_group;");                             \
    } while (0)

    // ---- ldmatrix lane coordinates -----------------------------------------
    const int rA = w * 16 + (lane & 15);
    const int cA = (lane >> 4) << 2;       // 0 or 4
    const int xA = (rA & 7) * 4;
    const int nBlow = (lane & 7) + ((lane >> 4) & 1) * 8;   // + p*16
    const int cB    = ((lane >> 3) & 1) * 4;                // 0 or 4

    // prologue: fill STAGES-1 stages
    STAGE(0); STAGE(1); STAGE(2);

    for (int it = 0; it < NITER; ++it) {
        asm volatile("cp.async.wait_group %0;" :: "n"(STAGES - 2));
        __syncthreads();

        if (it + STAGES - 1 < NITER) STAGE(it + STAGES - 1);

        const uint32_t sb = smemBase + (it % STAGES) * STAGE_BYTES;
        const uint32_t aB = sb;
        const uint32_t bB = sb + A_BYTES;

        #pragma unroll
        for (int k8 = 0; k8 < 4; ++k8) {
            uint32_t a0, a1, a2, a3;
            ldsm4(a0, a1, a2, a3,
                  aB + (uint32_t)(rA * TK + ((k8 * 8 + cA) ^ xA)) * 4u);
            a0 = u2tf(a0); a1 = u2tf(a1); a2 = u2tf(a2); a3 = u2tf(a3);

            uint32_t bf[4][4];
            #pragma unroll
            for (int p = 0; p < 4; ++p) {
                int n = p * 16 + nBlow;
                ldsm4(bf[p][0], bf[p][1], bf[p][2], bf[p][3],
                      bB + (uint32_t)(n * TK + ((k8 * 8 + cB) ^ ((n & 7) * 4))) * 4u);
                #pragma unroll
                for (int j = 0; j < 4; ++j) bf[p][j] = u2tf(bf[p][j]);
            }

            #pragma unroll
            for (int nt = 0; nt < 8; ++nt)
                mma_tf32(acc[nt], a0, a1, a2, a3,
                         bf[nt >> 1][(nt & 1) * 2], bf[nt >> 1][(nt & 1) * 2 + 1]);
        }
        // No trailing sync needed: STAGE(it+STAGES-1) (issued after the top
        // barrier of iteration it) writes buffer (it-1)%STAGES, whose readers
        // all passed that same barrier.
    }

    // ---- epilogue: gate(r) * acc + bq ----
    const float wr0 = Wr[0], wr1 = Wr[1], wr2 = Wr[2], wr3 = Wr[3];
    const float brv = br[0];

    const int rbase = bm * TM + w * 16 + (lane >> 2);
    #pragma unroll
    for (int h = 0; h < 2; ++h) {
        const int row = rbase + h * 8;
        const float rf = (float)rdat[row];
        float s = brv;
        s += fmaxf(1.0f - fabsf(0.0f - rf) * (1.0f / 3.0f), 0.0f) * wr0;
        s += fmaxf(1.0f - fabsf(1.0f - rf) * (1.0f / 3.0f), 0.0f) * wr1;
        s += fmaxf(1.0f - fabsf(2.0f - rf) * (1.0f / 3.0f), 0.0f) * wr2;
        s += fmaxf(1.0f - fabsf(3.0f - rf) * (1.0f / 3.0f), 0.0f) * wr3;
        const float gate = 1.0f / (1.0f + expf(-s));

        #pragma unroll
        for (int nt = 0; nt < 8; ++nt) {
            const int col = nt * 8 + (lane & 3) * 2;
            float2 v;
            v.x = acc[nt][h * 2 + 0] * gate + bq[col];
            v.y = acc[nt][h * 2 + 1] * gate + bq[col + 1];
            *reinterpret_cast<float2*>(out + (size_t)row * NDIM + col) = v;
        }
    }
}

// ---------------------------------------------------------------------------
// launch
// ---------------------------------------------------------------------------
extern "C" void kernel_launch(void* const* d_in, const int* in_sizes, int n_in,
                              void* d_out, int out_size) {
    const float* q    = (const float*)d_in[0];   // [64,512,800] f32
    const int*   rdat = (const int*)  d_in[1];   // [64,512]     i32
    const float* Wq   = (const float*)d_in[2];   // [64,800]     f32
    const float* bq   = (const float*)d_in[3];   // [64]         f32
    const float* Wr   = (const float*)d_in[4];   // [1,4]        f32
    const float* br   = (const float*)d_in[5];   // [1]          f32
    float* out = (float*)d_out;                  // [64,512,64]  f32

    cudaFuncSetAttribute(ordinal_embed_kernel,
                         cudaFuncAttributeMaxDynamicSharedMemorySize, SMEM_TOTAL);
    ordinal_embed_kernel<<<MDIM / TM, THREADS, SMEM_TOTAL>>>(q, rdat, Wq, bq, Wr, br, out);
}